// round 15
// baseline (speedup 1.0000x reference)
#include <cuda_runtime.h>
#include <cuda_bf16.h>
#include <mma.h>
#include <cstdint>

#define NPTS   80000
#define NDPTS  10000
#define KOFF   27

typedef unsigned long long ull;
typedef unsigned int u32;

using namespace nvcuda;

// ---------------- packed fp32x2 helpers ----------------
__device__ __forceinline__ ull ffma2(ull a, ull b, ull c) {
    ull d;
    asm("fma.rn.f32x2 %0, %1, %2, %3;" : "=l"(d) : "l"(a), "l"(b), "l"(c));
    return d;
}
__device__ __forceinline__ ull pack2(float v) {
    ull d;
    asm("mov.b64 %0, {%1, %1};" : "=l"(d) : "f"(v));
    return d;
}
__device__ __forceinline__ ull packf2(float a, float b) {
    ull d;
    asm("mov.b64 %0, {%1, %2};" : "=l"(d) : "f"(a), "f"(b));
    return d;
}
__device__ __forceinline__ float2 unpack2(ull v) {
    float2 r;
    asm("mov.b64 {%0, %1}, %2;" : "=f"(r.x), "=f"(r.y) : "l"(v));
    return r;
}

// ---------------- scratch buffers ----------------
__device__ float g_y3d [NPTS * 16];
__device__ float g_c2d [NPTS * 64];
__device__ float g_mix [NPTS * 80];
__device__ float g_h   [NPTS * 80];

__device__ __align__(16) __nv_bfloat16 g_p2h [NPTS * 64];
__device__ __align__(16) __nv_bfloat16 g_p2l [NPTS * 64];
__device__ __align__(16) __nv_bfloat16 g_mixh[NPTS * 80];
__device__ __align__(16) __nv_bfloat16 g_mixl[NPTS * 80];
__device__ __align__(16) __nv_bfloat16 g_th  [NPTS * 80];
__device__ __align__(16) __nv_bfloat16 g_tl  [NPTS * 80];
__device__ __align__(16) __nv_bfloat16 g_hh  [NPTS * 80];
__device__ __align__(16) __nv_bfloat16 g_hl  [NPTS * 80];
__device__ __align__(16) __nv_bfloat16 g_ah  [NPTS * 80];
__device__ __align__(16) __nv_bfloat16 g_al  [NPTS * 80];

// transposed/split weights [27][COUT][CIN] bf16
__device__ __align__(16) __nv_bfloat16 g_w2h [KOFF * 64 * 64];
__device__ __align__(16) __nv_bfloat16 g_w2l [KOFF * 64 * 64];
__device__ __align__(16) __nv_bfloat16 g_wm1h[KOFF * 80 * 80];
__device__ __align__(16) __nv_bfloat16 g_wm1l[KOFF * 80 * 80];
__device__ __align__(16) __nv_bfloat16 g_wm2h[KOFF * 80 * 80];
__device__ __align__(16) __nv_bfloat16 g_wm2l[KOFF * 80 * 80];
__device__ __align__(16) __nv_bfloat16 g_wa1h[KOFF * 80 * 80];
__device__ __align__(16) __nv_bfloat16 g_wa1l[KOFF * 80 * 80];
__device__ __align__(16) __nv_bfloat16 g_wa2h[KOFF * 80 * 80];
__device__ __align__(16) __nv_bfloat16 g_wa2l[KOFF * 80 * 80];
__device__ __align__(16) __nv_bfloat16 g_wdsh[KOFF * 96 * 80];
__device__ __align__(16) __nv_bfloat16 g_wdsl[KOFF * 96 * 80];
// Wp transposed/split: [64][320] (k padded 259->320, zeros)
__device__ __align__(16) __nv_bfloat16 g_wph [64 * 320];
__device__ __align__(16) __nv_bfloat16 g_wpl [64 * 320];

__device__ __forceinline__ void split_bf16(float v, __nv_bfloat16& h, __nv_bfloat16& l) {
    h = __float2bfloat16(v);
    l = __float2bfloat16(v - __bfloat162float(h));
}

// =====================================================================
// prep: W [27][CIN][COUT] fp32 -> Wt hi/lo [27][COUT][CIN] bf16
// =====================================================================
__global__ void prep_w(const float* __restrict__ W,
                       __nv_bfloat16* __restrict__ Wh,
                       __nv_bfloat16* __restrict__ Wl, int CIN, int COUT)
{
    int tot = KOFF * CIN * COUT;
    for (int i = blockIdx.x * blockDim.x + threadIdx.x; i < tot;
         i += gridDim.x * blockDim.x) {
        int k = i / (CIN * COUT);
        int rem = i - k * (CIN * COUT);
        int c = rem / COUT, n = rem - c * COUT;
        float v = W[i];
        __nv_bfloat16 h, l;
        split_bf16(v, h, l);
        int o = (k * COUT + n) * CIN + c;
        Wh[o] = h; Wl[o] = l;
    }
}

// prep Wp [259][64] fp32 -> [64][320] hi/lo bf16 (zero-padded k>=259)
__global__ void prep_wp(const float* __restrict__ Wp,
                        __nv_bfloat16* __restrict__ Wh,
                        __nv_bfloat16* __restrict__ Wl)
{
    int i = blockIdx.x * blockDim.x + threadIdx.x;
    if (i >= 64 * 320) return;
    int nrow = i / 320, k = i - nrow * 320;
    float v = (k < 259) ? Wp[k * 64 + nrow] : 0.f;
    __nv_bfloat16 h, l;
    split_bf16(v, h, l);
    Wh[i] = h; Wl[i] = l;
}

// =====================================================================
// conv16 (SIMT) -> y3d fp32, mix[:,0:16] fp32 + bf16 hi/lo
// =====================================================================
__global__ void __launch_bounds__(256)
conv16_kernel(const float* __restrict__ x, const int* __restrict__ nbr,
              const float* __restrict__ W, const float* __restrict__ gamma,
              const float* __restrict__ beta,
              float* __restrict__ y3d, float* __restrict__ mix,
              __nv_bfloat16* __restrict__ mixh, __nv_bfloat16* __restrict__ mixl,
              int n)
{
    __shared__ float Wsh[KOFF * 16 * 16];
    for (int t = threadIdx.x; t < KOFF * 64; t += 256)
        ((float4*)Wsh)[t] = ((const float4*)W)[t];
    __syncthreads();

    int row = blockIdx.x * 256 + threadIdx.x;
    if (row >= n) return;

    ull acc[8];
#pragma unroll
    for (int p = 0; p < 8; p++) acc[p] = 0ull;

    const int* nb = nbr + (size_t)row * KOFF;
    for (int k = 0; k < KOFF; k++) {
        int idx = __ldg(nb + k);
        if (idx < 0) continue;
        const float* f = x + (size_t)idx * 16;
#pragma unroll
        for (int cq = 0; cq < 4; cq++) {
            float4 a = *(const float4*)(f + 4 * cq);
#pragma unroll
            for (int cc = 0; cc < 4; cc++) {
                float fv = (cc == 0) ? a.x : (cc == 1) ? a.y : (cc == 2) ? a.z : a.w;
                ull p2 = pack2(fv);
                const ulonglong2* br =
                    (const ulonglong2*)(Wsh + (k * 16 + cq * 4 + cc) * 16);
#pragma unroll
                for (int q = 0; q < 4; q++) {
                    ulonglong2 b = br[q];
                    acc[2*q]   = ffma2(p2, b.x, acc[2*q]);
                    acc[2*q+1] = ffma2(p2, b.y, acc[2*q+1]);
                }
            }
        }
    }
    float* yo = y3d + (size_t)row * 16;
    float* mo = mix + (size_t)row * 80;
    __nv_bfloat16* mh = mixh + (size_t)row * 80;
    __nv_bfloat16* ml = mixl + (size_t)row * 80;
#pragma unroll
    for (int p = 0; p < 8; p++) {
        float2 v = unpack2(acc[p]);
        int j = 2 * p;
        float v0 = fmaxf(v.x * __ldg(gamma + j)     + __ldg(beta + j),     0.f);
        float v1 = fmaxf(v.y * __ldg(gamma + j + 1) + __ldg(beta + j + 1), 0.f);
        float2 o = make_float2(v0, v1);
        *(float2*)(yo + j) = o;
        *(float2*)(mo + j) = o;
        __nv_bfloat16 h0, l0, h1, l1;
        split_bf16(v0, h0, l0);
        split_bf16(v1, h1, l1);
        mh[j] = h0; mh[j+1] = h1;
        ml[j] = l0; ml[j+1] = l1;
    }
}

// =====================================================================
// gate2w: fused dual gate with WMMA projection.
// Block 128 thr / 4 warps / 64 rows. K chunks of 64 (259 padded -> 320).
// Per chunk: SIMT compute S_gate hi/lo -> MMA accP; S_cross -> MMA accC.
//   s_j = relu(y3d·Wsel_j + b_j) * f2g_j ; out = S @ Wp (bf16x3 wmma).
// =====================================================================
#define GW_WSG   0
#define GW_WSC   4160
#define GW_BG    8320
#define GW_BC    8580
#define GW_SOFF  8840                     // float offset; byte 35360 (16B ok)
#define GW_FLOATS 18056                   // 72224 bytes total

__global__ void __launch_bounds__(128)
gate2w_kernel(const float* __restrict__ y3d, const float* __restrict__ f2d,
              const int* __restrict__ nn_idx,
              const float* __restrict__ Wg, const float* __restrict__ bg,
              const float* __restrict__ Wc, const float* __restrict__ bc,
              const __nv_bfloat16* __restrict__ wph,
              const __nv_bfloat16* __restrict__ wpl,
              __nv_bfloat16* __restrict__ p2h, __nv_bfloat16* __restrict__ p2l,
              float* __restrict__ c2d, int n)
{
    extern __shared__ float sh[];
    float* WsG = sh + GW_WSG;   // [260][16]
    float* WsC = sh + GW_WSC;
    float* bG  = sh + GW_BG;    // [260]
    float* bC  = sh + GW_BC;
    __nv_bfloat16* Sh  = (__nv_bfloat16*)(sh + GW_SOFF);        // [64][72]
    __nv_bfloat16* Sl  = Sh + 64 * 72;                           // [64][72]
    __nv_bfloat16* Wph = Sl + 64 * 72;                           // [64][72]
    __nv_bfloat16* Wpl = Wph + 64 * 72;                          // [64][72]

    const int tid  = threadIdx.x;
    const int warp = tid >> 5;
    const int r    = tid >> 1;        // local row 0..63
    const int half = tid & 1;         // j-half within chunk
    const int row  = blockIdx.x * 64 + r;
    const int m0   = warp * 16;

    for (int t = tid; t < 259 * 16; t += 128) {
        int c = t / 259, j = t - c * 259;
        WsG[j * 16 + c] = Wg[t];
        WsC[j * 16 + c] = Wc[t];
    }
    for (int t = tid; t < 259; t += 128) { bG[t] = bg[t]; bC[t] = bc[t]; }
    __syncthreads();

    const bool rowok = (row < n);
    const int fi = rowok ? nn_idx[row] : -1;
    ull y2[8];
    if (fi >= 0) {
#pragma unroll
        for (int cq = 0; cq < 4; cq++) {
            float4 v = *(const float4*)(y3d + (size_t)row * 16 + 4 * cq);
            y2[2*cq]   = packf2(v.x, v.y);
            y2[2*cq+1] = packf2(v.z, v.w);
        }
    } else {
#pragma unroll
        for (int q = 0; q < 8; q++) y2[q] = 0ull;
    }
    const float* fr = (fi >= 0) ? (f2d + (size_t)fi * 259) : nullptr;

    wmma::fragment<wmma::accumulator, 16, 16, 16, float> accP[4], accC[4];
#pragma unroll
    for (int nn = 0; nn < 4; nn++) {
        wmma::fill_fragment(accP[nn], 0.f);
        wmma::fill_fragment(accC[nn], 0.f);
    }

    for (int ch = 0; ch < 5; ch++) {
        // stage Wp chunk (both planes)
        for (int e = tid; e < 64 * 8; e += 128) {
            int nrow = e >> 3, c = e & 7;
            const __nv_bfloat16* sh_ = wph + nrow * 320 + ch * 64 + c * 8;
            const __nv_bfloat16* sl_ = wpl + nrow * 320 + ch * 64 + c * 8;
            *(uint4*)(Wph + nrow * 72 + c * 8) = *(const uint4*)sh_;
            *(uint4*)(Wpl + nrow * 72 + c * 8) = *(const uint4*)sl_;
        }

        // -------- phase G --------
        {
            __nv_bfloat16* dh = Sh + r * 72 + half * 32;
            __nv_bfloat16* dl = Sl + r * 72 + half * 32;
            int jb = ch * 64 + half * 32;
#pragma unroll 4
            for (int jj = 0; jj < 32; jj++) {
                int jg = jb + jj;
                float s = 0.f;
                if (fi >= 0 && jg < 259) {
                    const ulonglong2* wv = (const ulonglong2*)(WsG + jg * 16);
                    ull d2 = 0ull;
#pragma unroll
                    for (int q = 0; q < 4; q++) {
                        ulonglong2 w = wv[q];
                        d2 = ffma2(y2[2*q],   w.x, d2);
                        d2 = ffma2(y2[2*q+1], w.y, d2);
                    }
                    float2 dd = unpack2(d2);
                    s = fmaxf(dd.x + dd.y + bG[jg], 0.f) * __ldg(fr + jg);
                }
                __nv_bfloat16 h, l;
                split_bf16(s, h, l);
                dh[jj] = h; dl[jj] = l;
            }
        }
        __syncthreads();
#pragma unroll
        for (int kk = 0; kk < 4; kk++) {
            wmma::fragment<wmma::matrix_a, 16, 16, 16, __nv_bfloat16,
                           wmma::row_major> Ah, Al;
            wmma::load_matrix_sync(Ah, Sh + m0 * 72 + kk * 16, 72);
            wmma::load_matrix_sync(Al, Sl + m0 * 72 + kk * 16, 72);
#pragma unroll
            for (int nn = 0; nn < 4; nn++) {
                wmma::fragment<wmma::matrix_b, 16, 16, 16, __nv_bfloat16,
                               wmma::col_major> Bh, Bl;
                wmma::load_matrix_sync(Bh, Wph + nn * 16 * 72 + kk * 16, 72);
                wmma::load_matrix_sync(Bl, Wpl + nn * 16 * 72 + kk * 16, 72);
                wmma::mma_sync(accP[nn], Ah, Bh, accP[nn]);
                wmma::mma_sync(accP[nn], Ah, Bl, accP[nn]);
                wmma::mma_sync(accP[nn], Al, Bh, accP[nn]);
            }
        }
        __syncthreads();

        // -------- phase C --------
        {
            __nv_bfloat16* dh = Sh + r * 72 + half * 32;
            __nv_bfloat16* dl = Sl + r * 72 + half * 32;
            int jb = ch * 64 + half * 32;
#pragma unroll 4
            for (int jj = 0; jj < 32; jj++) {
                int jg = jb + jj;
                float s = 0.f;
                if (fi >= 0 && jg < 259) {
                    const ulonglong2* wv = (const ulonglong2*)(WsC + jg * 16);
                    ull d2 = 0ull;
#pragma unroll
                    for (int q = 0; q < 4; q++) {
                        ulonglong2 w = wv[q];
                        d2 = ffma2(y2[2*q],   w.x, d2);
                        d2 = ffma2(y2[2*q+1], w.y, d2);
                    }
                    float2 dd = unpack2(d2);
                    s = fmaxf(dd.x + dd.y + bC[jg], 0.f) * __ldg(fr + jg);
                }
                __nv_bfloat16 h, l;
                split_bf16(s, h, l);
                dh[jj] = h; dl[jj] = l;
            }
        }
        __syncthreads();
#pragma unroll
        for (int kk = 0; kk < 4; kk++) {
            wmma::fragment<wmma::matrix_a, 16, 16, 16, __nv_bfloat16,
                           wmma::row_major> Ah, Al;
            wmma::load_matrix_sync(Ah, Sh + m0 * 72 + kk * 16, 72);
            wmma::load_matrix_sync(Al, Sl + m0 * 72 + kk * 16, 72);
#pragma unroll
            for (int nn = 0; nn < 4; nn++) {
                wmma::fragment<wmma::matrix_b, 16, 16, 16, __nv_bfloat16,
                               wmma::col_major> Bh, Bl;
                wmma::load_matrix_sync(Bh, Wph + nn * 16 * 72 + kk * 16, 72);
                wmma::load_matrix_sync(Bl, Wpl + nn * 16 * 72 + kk * 16, 72);
                wmma::mma_sync(accC[nn], Ah, Bh, accC[nn]);
                wmma::mma_sync(accC[nn], Ah, Bl, accC[nn]);
                wmma::mma_sync(accC[nn], Al, Bh, accC[nn]);
            }
        }
        __syncthreads();
    }

    // -------- epilogue --------
    float* Cst = (float*)(sh + GW_SOFF);  // [64][68]
#pragma unroll
    for (int nn = 0; nn < 4; nn++)
        wmma::store_matrix_sync(Cst + m0 * 68 + nn * 16, accP[nn], 68,
                                wmma::mem_row_major);
    __syncthreads();
    for (int e = tid; e < 64 * 64; e += 128) {
        int rr = e >> 6, j = e & 63;
        int rw = blockIdx.x * 64 + rr;
        if (rw >= n) continue;
        __nv_bfloat16 h, l;
        split_bf16(Cst[rr * 68 + j], h, l);
        p2h[(size_t)rw * 64 + j] = h;
        p2l[(size_t)rw * 64 + j] = l;
    }
    __syncthreads();
#pragma unroll
    for (int nn = 0; nn < 4; nn++)
        wmma::store_matrix_sync(Cst + m0 * 68 + nn * 16, accC[nn], 68,
                                wmma::mem_row_major);
    __syncthreads();
    for (int e = tid; e < 64 * 64; e += 128) {
        int rr = e >> 6, j = e & 63;
        int rw = blockIdx.x * 64 + rr;
        if (rw >= n) continue;
        c2d[(size_t)rw * 64 + j] = Cst[rr * 68 + j];
    }
}

// =====================================================================
// WMMA conv (R12-proven + row guard): bf16x3 split, fp32 acc.
// Block = 128 thr / 4 warps / 128 rows.
// EPI 0: relu(v*g+b)  EPI 1: relu(v*g+b)+res  EPI 2: relu(v*g+b+res)
// =====================================================================
template <int CIN, int COUT, int EPI>
__global__ void __launch_bounds__(128)
wmmaconv_kernel(const __nv_bfloat16* __restrict__ fh,
                const __nv_bfloat16* __restrict__ fl,
                const int* __restrict__ nbr,
                const __nv_bfloat16* __restrict__ wh,
                const __nv_bfloat16* __restrict__ wl,
                const float* __restrict__ gamma, const float* __restrict__ beta,
                const float* __restrict__ res, int resStride, int resCol0,
                float* __restrict__ outF, int ofStride, int ofCol0,
                __nv_bfloat16* __restrict__ outH, __nv_bfloat16* __restrict__ outL,
                int obStride, int obCol0, int n)
{
    constexpr int KT  = CIN / 16;
    constexpr int NT  = COUT / 16;
    constexpr int SP  = CIN + 8;
    constexpr int NCH = CIN / 8;
    constexpr int CP  = COUT + 4;

    extern __shared__ char sm[];
    __nv_bfloat16* Fh = (__nv_bfloat16*)sm;
    __nv_bfloat16* Fl = Fh + 128 * SP;
    __nv_bfloat16* Wh = Fl + 128 * SP;
    __nv_bfloat16* Wl = Wh + COUT * SP;

    const int tid  = threadIdx.x;
    const int warp = tid >> 5;
    const int rowbase = blockIdx.x * 128;
    const int m0 = warp * 32;

    wmma::fragment<wmma::accumulator, 16, 16, 16, float> acc[2][NT];
#pragma unroll
    for (int m = 0; m < 2; m++)
#pragma unroll
        for (int nn = 0; nn < NT; nn++) wmma::fill_fragment(acc[m][nn], 0.f);

    for (int k = 0; k < KOFF; k++) {
        __syncthreads();
        for (int e = tid; e < 128 * NCH; e += 128) {
            int r = e / NCH, c = e - r * NCH;
            int row = rowbase + r;
            int idx = (row < n) ? __ldg(nbr + (size_t)row * KOFF + k) : -1;
            uint4 vh = make_uint4(0, 0, 0, 0), vl = vh;
            if (idx >= 0) {
                const char* ph = (const char*)(fh + (size_t)idx * CIN) + c * 16;
                const char* pl = (const char*)(fl + (size_t)idx * CIN) + c * 16;
                vh = *(const uint4*)ph;
                vl = *(const uint4*)pl;
            }
            *(uint4*)((char*)(Fh + r * SP) + c * 16) = vh;
            *(uint4*)((char*)(Fl + r * SP) + c * 16) = vl;
        }
        {
            const char* whk = (const char*)(wh + (size_t)k * COUT * CIN);
            const char* wlk = (const char*)(wl + (size_t)k * COUT * CIN);
            for (int e = tid; e < COUT * NCH; e += 128) {
                int r = e / NCH, c = e - r * NCH;
                uint4 vh = *(const uint4*)(whk + (size_t)r * CIN * 2 + c * 16);
                uint4 vl = *(const uint4*)(wlk + (size_t)r * CIN * 2 + c * 16);
                *(uint4*)((char*)(Wh + r * SP) + c * 16) = vh;
                *(uint4*)((char*)(Wl + r * SP) + c * 16) = vl;
            }
        }
        __syncthreads();

#pragma unroll
        for (int kk = 0; kk < KT; kk++) {
            wmma::fragment<wmma::matrix_a, 16, 16, 16, __nv_bfloat16,
                           wmma::row_major> Ah[2], Al[2];
#pragma unroll
            for (int m = 0; m < 2; m++) {
                wmma::load_matrix_sync(Ah[m], Fh + (m0 + m * 16) * SP + kk * 16, SP);
                wmma::load_matrix_sync(Al[m], Fl + (m0 + m * 16) * SP + kk * 16, SP);
            }
#pragma unroll
            for (int nn = 0; nn < NT; nn++) {
                wmma::fragment<wmma::matrix_b, 16, 16, 16, __nv_bfloat16,
                               wmma::col_major> Bh, Bl;
                wmma::load_matrix_sync(Bh, Wh + nn * 16 * SP + kk * 16, SP);
                wmma::load_matrix_sync(Bl, Wl + nn * 16 * SP + kk * 16, SP);
#pragma unroll
                for (int m = 0; m < 2; m++) {
                    wmma::mma_sync(acc[m][nn], Ah[m], Bh, acc[m][nn]);
                    wmma::mma_sync(acc[m][nn], Ah[m], Bl, acc[m][nn]);
                    wmma::mma_sync(acc[m][nn], Al[m], Bh, acc[m][nn]);
                }
            }
        }
    }

    __syncthreads();
    float* C = (float*)sm;
#pragma unroll
    for (int m = 0; m < 2; m++)
#pragma unroll
        for (int nn = 0; nn < NT; nn++)
            wmma::store_matrix_sync(C + (m0 + m * 16) * CP + nn * 16,
                                    acc[m][nn], CP, wmma::mem_row_major);
    __syncthreads();

    for (int e = tid; e < 128 * COUT; e += 128) {
        int r = e / COUT, j = e - r * COUT;
        int row = rowbase + r;
        if (row >= n) continue;
        float v = C[r * CP + j] * __ldg(gamma + j) + __ldg(beta + j);
        float rv = 0.f;
        if (EPI != 0) rv = res[(size_t)row * resStride + resCol0 + j];
        if (EPI == 2) v += rv;
        v = fmaxf(v, 0.f);
        if (EPI == 1) v += rv;
        if (outF) outF[(size_t)row * ofStride + ofCol0 + j] = v;
        if (outH) {
            __nv_bfloat16 h, l;
            split_bf16(v, h, l);
            outH[(size_t)row * obStride + obCol0 + j] = h;
            outL[(size_t)row * obStride + obCol0 + j] = l;
        }
    }
}

#define SMEM_W64   ((2 * 128 * 72 + 2 * 64 * 72) * 2)   // 55296
#define SMEM_W80   ((2 * 128 * 88 + 2 * 80 * 88) * 2)   // 73216
#define SMEM_W96   ((2 * 128 * 88 + 2 * 96 * 88) * 2)   // 78848

// =====================================================================
// Launch
// =====================================================================
extern "C" void kernel_launch(void* const* d_in, const int* in_sizes, int n_in,
                              void* d_out, int out_size)
{
    const float* x3d    = (const float*)d_in[0];
    const float* f2d    = (const float*)d_in[1];
    const int*   nn_idx = (const int*)  d_in[2];
    const int*   nbr    = (const int*)  d_in[3];
    const int*   nbr_ds = (const int*)  d_in[4];
    const float* W3d    = (const float*)d_in[5];
    const float* g3d    = (const float*)d_in[6];
    const float* b3d    = (const float*)d_in[7];
    const float* Wg     = (const float*)d_in[8];
    const float* bg     = (const float*)d_in[9];
    const float* Wc     = (const float*)d_in[10];
    const float* bc     = (const float*)d_in[11];
    const float* Wp     = (const float*)d_in[12];
    const float* W2d    = (const float*)d_in[13];
    const float* g2d    = (const float*)d_in[14];
    const float* b2d    = (const float*)d_in[15];
    const float* Wm1    = (const float*)d_in[16];
    const float* gm1    = (const float*)d_in[17];
    const float* bm1    = (const float*)d_in[18];
    const float* Wm2    = (const float*)d_in[19];
    const float* gm2    = (const float*)d_in[20];
    const float* bm2    = (const float*)d_in[21];
    const float* Wa1    = (const float*)d_in[22];
    const float* ga1    = (const float*)d_in[23];
    const float* ba1    = (const float*)d_in[24];
    const float* Wa2    = (const float*)d_in[25];
    const float* ga2    = (const float*)d_in[26];
    const float* ba2    = (const float*)d_in[27];
    const float* Wds    = (const float*)d_in[28];
    const float* gds    = (const float*)d_in[29];
    const float* bds    = (const float*)d_in[30];
    float* out = (float*)d_out;

    float *y3d, *c2d, *mix, *hbuf;
    cudaGetSymbolAddress((void**)&y3d,  g_y3d);
    cudaGetSymbolAddress((void**)&c2d,  g_c2d);
    cudaGetSymbolAddress((void**)&mix,  g_mix);
    cudaGetSymbolAddress((void**)&hbuf, g_h);

    __nv_bfloat16 *p2h, *p2l, *mixh, *mixl, *th, *tl, *hh, *hl, *ah, *al;
    cudaGetSymbolAddress((void**)&p2h,  g_p2h);
    cudaGetSymbolAddress((void**)&p2l,  g_p2l);
    cudaGetSymbolAddress((void**)&mixh, g_mixh);
    cudaGetSymbolAddress((void**)&mixl, g_mixl);
    cudaGetSymbolAddress((void**)&th,   g_th);
    cudaGetSymbolAddress((void**)&tl,   g_tl);
    cudaGetSymbolAddress((void**)&hh,   g_hh);
    cudaGetSymbolAddress((void**)&hl,   g_hl);
    cudaGetSymbolAddress((void**)&ah,   g_ah);
    cudaGetSymbolAddress((void**)&al,   g_al);

    __nv_bfloat16 *w2h, *w2l, *wm1h, *wm1l, *wm2h, *wm2l, *wa1h, *wa1l,
                  *wa2h, *wa2l, *wdsh, *wdsl, *wph, *wpl;
    cudaGetSymbolAddress((void**)&w2h,  g_w2h);
    cudaGetSymbolAddress((void**)&w2l,  g_w2l);
    cudaGetSymbolAddress((void**)&wm1h, g_wm1h);
    cudaGetSymbolAddress((void**)&wm1l, g_wm1l);
    cudaGetSymbolAddress((void**)&wm2h, g_wm2h);
    cudaGetSymbolAddress((void**)&wm2l, g_wm2l);
    cudaGetSymbolAddress((void**)&wa1h, g_wa1h);
    cudaGetSymbolAddress((void**)&wa1l, g_wa1l);
    cudaGetSymbolAddress((void**)&wa2h, g_wa2h);
    cudaGetSymbolAddress((void**)&wa2l, g_wa2l);
    cudaGetSymbolAddress((void**)&wdsh, g_wdsh);
    cudaGetSymbolAddress((void**)&wdsl, g_wdsl);
    cudaGetSymbolAddress((void**)&wph,  g_wph);
    cudaGetSymbolAddress((void**)&wpl,  g_wpl);

    cudaFuncSetAttribute(gate2w_kernel, cudaFuncAttributeMaxDynamicSharedMemorySize,
                         GW_FLOATS * (int)sizeof(float));
    cudaFuncSetAttribute(wmmaconv_kernel<64, 64, 1>,
                         cudaFuncAttributeMaxDynamicSharedMemorySize, SMEM_W64);
    cudaFuncSetAttribute(wmmaconv_kernel<80, 80, 0>,
                         cudaFuncAttributeMaxDynamicSharedMemorySize, SMEM_W80);
    cudaFuncSetAttribute(wmmaconv_kernel<80, 80, 2>,
                         cudaFuncAttributeMaxDynamicSharedMemorySize, SMEM_W80);
    cudaFuncSetAttribute(wmmaconv_kernel<80, 96, 0>,
                         cudaFuncAttributeMaxDynamicSharedMemorySize, SMEM_W96);

    const int B256 = (NPTS + 255) / 256;
    const int BC   = NPTS / 128;            // 625 (exact)
    const int BG   = NPTS / 64;             // 1250 (exact)
    const int BDS  = (NDPTS + 127) / 128;   // 79 (guarded)

    // 0. weight transforms
    prep_w<<<(KOFF*64*64 + 255)/256, 256>>>(W2d, w2h, w2l, 64, 64);
    prep_w<<<(KOFF*80*80 + 255)/256, 256>>>(Wm1, wm1h, wm1l, 80, 80);
    prep_w<<<(KOFF*80*80 + 255)/256, 256>>>(Wm2, wm2h, wm2l, 80, 80);
    prep_w<<<(KOFF*80*80 + 255)/256, 256>>>(Wa1, wa1h, wa1l, 80, 80);
    prep_w<<<(KOFF*80*80 + 255)/256, 256>>>(Wa2, wa2h, wa2l, 80, 80);
    prep_w<<<(KOFF*80*96 + 255)/256, 256>>>(Wds, wdsh, wdsl, 80, 96);
    prep_wp<<<(64*320 + 255)/256, 256>>>(Wp, wph, wpl);

    // 1. y3d + mix[:,0:16]
    conv16_kernel<<<B256, 256>>>(x3d, nbr, W3d, g3d, b3d, y3d, mix, mixh, mixl, NPTS);

    // 2. fused dual gate (WMMA projection): p2d (bf16 hi/lo) + c2d (fp32)
    gate2w_kernel<<<BG, 128, GW_FLOATS * sizeof(float)>>>(
        y3d, f2d, nn_idx, Wg, bg, Wc, bc, wph, wpl, p2h, p2l, c2d, NPTS);

    // 3. mix[:,16:80] = bn_relu(conv64(p2d)) + c2d
    wmmaconv_kernel<64, 64, 1><<<BC, 128, SMEM_W64>>>(
        p2h, p2l, nbr, w2h, w2l, g2d, b2d,
        c2d, 64, 0, mix, 80, 16, mixh, mixl, 80, 16, NPTS);

    // 4. t = bn_relu(conv80(mix, Wm1))
    wmmaconv_kernel<80, 80, 0><<<BC, 128, SMEM_W80>>>(
        mixh, mixl, nbr, wm1h, wm1l, gm1, bm1,
        nullptr, 0, 0, nullptr, 0, 0, th, tl, 80, 0, NPTS);

    // 5. h = relu(conv80(t, Wm2)*g + b + mix)
    wmmaconv_kernel<80, 80, 2><<<BC, 128, SMEM_W80>>>(
        th, tl, nbr, wm2h, wm2l, gm2, bm2,
        mix, 80, 0, hbuf, 80, 0, hh, hl, 80, 0, NPTS);

    // 6. t = bn_relu(conv80(h, Wa1))
    wmmaconv_kernel<80, 80, 0><<<BC, 128, SMEM_W80>>>(
        hh, hl, nbr, wa1h, wa1l, ga1, ba1,
        nullptr, 0, 0, nullptr, 0, 0, th, tl, 80, 0, NPTS);

    // 7. a = relu(conv80(t, Wa2)*g + b + h)  (bf16 hi/lo only)
    wmmaconv_kernel<80, 80, 2><<<BC, 128, SMEM_W80>>>(
        th, tl, nbr, wa2h, wa2l, ga2, ba2,
        hbuf, 80, 0, nullptr, 0, 0, ah, al, 80, 0, NPTS);

    // 8. out = bn_relu(conv80->96(a, nbr_ds, Wds))  (WMMA, guarded rows)
    wmmaconv_kernel<80, 96, 0><<<BDS, 128, SMEM_W96>>>(
        ah, al, nbr_ds, wdsh, wdsl, gds, bds,
        nullptr, 0, 0, out, 96, 0, nullptr, nullptr, 0, 0, NDPTS);
}